// round 4
// baseline (speedup 1.0000x reference)
#include <cuda_runtime.h>

// GATv3Psi: per-edge logits -> (shift-free) segment softmax over dst -> aggregate.
// d_out layout: out[N], attn[E], pair_pred[E,2].

#define K2 16              // 2 * K_EIG
static const int NMAX = 100000;
static const int EMAX = 3200000;

__device__ int    g_is64;
__device__ int    g_dst32[EMAX];
__device__ float  g_ex[EMAX];            // exp(score)
__device__ float2 g_dn[NMAX];            // .x = den, .y = num (single red.v2 target)
__device__ float  g_invden[NMAX];

__device__ __forceinline__ void red_add_v2(float2* addr, float a, float b) {
    asm volatile("red.global.add.v2.f32 [%0], {%1, %2};"
                 :: "l"(addr), "f"(a), "f"(b) : "memory");
}

// Detect int64 vs int32 edge_index (JAX x64-disabled silently downcasts).
__global__ void k_detect(const void* ei, int N) {
    const long long* p = (const long long*)ei;
    int ok = 1;
    #pragma unroll
    for (int i = 0; i < 8; i++) {
        long long v = p[i];
        if (v < 0 || v >= (long long)N) { ok = 0; break; }
    }
    g_is64 = ok;
}

__global__ void k_init(int N) {
    int i = blockIdx.x * blockDim.x + threadIdx.x;
    if (i < N) g_dn[i] = make_float2(0.0f, 0.0f);
}

// Pass A: 2 edges/thread. Logits, pair_pred, ex=exp(l0-l1);
// one red.v2 {ex, ex*w0*xs} to g_dn[d] per edge; emit int32 dst + ex for pass B.
__global__ __launch_bounds__(256) void k_passA(
        const float* __restrict__ x,
        const void*  __restrict__ ei,
        const float* __restrict__ ea,
        const float* __restrict__ W,
        const float* __restrict__ Wn,
        const float* __restrict__ We,
        float* __restrict__ pair_pred,
        int E, int write_pp) {
    __shared__ float sWe[K2 * 2];
    __shared__ float sWn[4];
    __shared__ float sW0;
    if (threadIdx.x < K2 * 2) sWe[threadIdx.x] = We[threadIdx.x];
    if (threadIdx.x >= 32 && threadIdx.x < 36) sWn[threadIdx.x - 32] = Wn[threadIdx.x - 32];
    if (threadIdx.x == 36) sW0 = W[0];
    __syncthreads();

    int e0 = (blockIdx.x * blockDim.x + threadIdx.x) * 2;
    if (e0 >= E) return;
    bool full = (e0 + 1 < E);

    int s0, d0, s1 = 0, d1 = 0;
    if (g_is64) {
        const long long* p = (const long long*)ei;
        if (full) {
            longlong2 sv = *(const longlong2*)(p + e0);
            longlong2 dv = *(const longlong2*)(p + (long long)E + e0);
            s0 = (int)sv.x; s1 = (int)sv.y; d0 = (int)dv.x; d1 = (int)dv.y;
        } else { s0 = (int)p[e0]; d0 = (int)p[(long long)E + e0]; }
    } else {
        const int* p = (const int*)ei;
        if (full) {
            int2 sv = *(const int2*)(p + e0);
            int2 dv = *(const int2*)(p + E + e0);
            s0 = sv.x; s1 = sv.y; d0 = dv.x; d1 = dv.y;
        } else { s0 = p[e0]; d0 = p[E + e0]; }
    }

    float xs0 = __ldg(&x[s0]);
    float xd0 = __ldg(&x[d0]);
    float xs1 = full ? __ldg(&x[s1]) : 0.0f;
    float xd1 = full ? __ldg(&x[d1]) : 0.0f;

    float a0 = xs0 * sWn[0] + xd0 * sWn[2];
    float b0 = xs0 * sWn[1] + xd0 * sWn[3];
    float a1 = xs1 * sWn[0] + xd1 * sWn[2];
    float b1 = xs1 * sWn[1] + xd1 * sWn[3];

    const float4* eap = (const float4*)(ea + (size_t)e0 * K2);
    #pragma unroll
    for (int i = 0; i < K2 / 4; i++) {
        float4 v = __ldg(&eap[i]);
        a0 = fmaf(v.x, sWe[(4*i+0)*2+0], a0);  b0 = fmaf(v.x, sWe[(4*i+0)*2+1], b0);
        a0 = fmaf(v.y, sWe[(4*i+1)*2+0], a0);  b0 = fmaf(v.y, sWe[(4*i+1)*2+1], b0);
        a0 = fmaf(v.z, sWe[(4*i+2)*2+0], a0);  b0 = fmaf(v.z, sWe[(4*i+2)*2+1], b0);
        a0 = fmaf(v.w, sWe[(4*i+3)*2+0], a0);  b0 = fmaf(v.w, sWe[(4*i+3)*2+1], b0);
    }
    if (full) {
        #pragma unroll
        for (int i = 0; i < K2 / 4; i++) {
            float4 v = __ldg(&eap[K2/4 + i]);
            a1 = fmaf(v.x, sWe[(4*i+0)*2+0], a1);  b1 = fmaf(v.x, sWe[(4*i+0)*2+1], b1);
            a1 = fmaf(v.y, sWe[(4*i+1)*2+0], a1);  b1 = fmaf(v.y, sWe[(4*i+1)*2+1], b1);
            a1 = fmaf(v.z, sWe[(4*i+2)*2+0], a1);  b1 = fmaf(v.z, sWe[(4*i+2)*2+1], b1);
            a1 = fmaf(v.w, sWe[(4*i+3)*2+0], a1);  b1 = fmaf(v.w, sWe[(4*i+3)*2+1], b1);
        }
    }

    a0 = fmaxf(a0, 0.2f * a0);  b0 = fmaxf(b0, 0.2f * b0);   // leaky_relu(., 0.2)
    a1 = fmaxf(a1, 0.2f * a1);  b1 = fmaxf(b1, 0.2f * b1);

    float ex0 = __expf(a0 - b0);
    float ex1 = __expf(a1 - b1);

    if (full) {
        if (write_pp) *(float4*)(pair_pred + (size_t)e0 * 2) = make_float4(a0, b0, a1, b1);
        *(float2*)&g_ex[e0]    = make_float2(ex0, ex1);
        *(int2*)  &g_dst32[e0] = make_int2(d0, d1);
        red_add_v2(&g_dn[d0], ex0, ex0 * sW0 * xs0);
        red_add_v2(&g_dn[d1], ex1, ex1 * sW0 * xs1);
    } else {
        if (write_pp) *(float2*)(pair_pred + (size_t)e0 * 2) = make_float2(a0, b0);
        g_ex[e0]    = ex0;
        g_dst32[e0] = d0;
        red_add_v2(&g_dn[d0], ex0, ex0 * sW0 * xs0);
    }
}

// Node pass: out[i] = num * inv; also stash inv for pass B.
__global__ void k_node(float* __restrict__ out, int N) {
    int i = blockIdx.x * blockDim.x + threadIdx.x;
    if (i < N) {
        float2 v = g_dn[i];
        float inv = 1.0f / (v.x + 1e-16f);
        g_invden[i] = inv;
        out[i] = v.y * inv;
    }
}

// Pass B: attn[e] = ex * inv_den[dst]. 4 edges/thread, vectorized.
__global__ __launch_bounds__(256) void k_passB(float* __restrict__ attn, int E) {
    int e = (blockIdx.x * blockDim.x + threadIdx.x) * 4;
    if (e + 3 < E) {
        float4 ex = *(const float4*)&g_ex[e];
        int4   d  = *(const int4*)&g_dst32[e];
        float4 a;
        a.x = ex.x * __ldg(&g_invden[d.x]);
        a.y = ex.y * __ldg(&g_invden[d.y]);
        a.z = ex.z * __ldg(&g_invden[d.z]);
        a.w = ex.w * __ldg(&g_invden[d.w]);
        *(float4*)&attn[e] = a;
    } else {
        for (; e < E; e++) attn[e] = g_ex[e] * __ldg(&g_invden[g_dst32[e]]);
    }
}

extern "C" void kernel_launch(void* const* d_in, const int* in_sizes, int n_in,
                              void* d_out, int out_size) {
    const float* x  = (const float*)d_in[0];
    const void*  ei = d_in[1];
    const float* ea = (const float*)d_in[2];
    const float* W  = (const float*)d_in[3];
    const float* Wn = (const float*)d_in[4];
    const float* We = (const float*)d_in[5];

    int N = in_sizes[0];          // x is [N, 1]
    int E = in_sizes[2] / K2;     // edge_attr is [E, 16]

    float* out  = (float*)d_out;
    float* attn = out + N;
    float* pp   = attn + E;
    int write_attn = (out_size >= N + E)     ? 1 : 0;
    int write_pp   = (out_size >= N + 3 * E) ? 1 : 0;

    const int T = 256;
    int gN = (N + T - 1) / T;
    int gA = ((E + 1) / 2 + T - 1) / T;
    int gB = (E / 4 + T) / T;

    k_detect<<<1, 1>>>(ei, N);
    k_init  <<<gN, T>>>(N);
    k_passA <<<gA, T>>>(x, ei, ea, W, Wn, We, pp, E, write_pp);
    k_node  <<<gN, T>>>(out, N);
    if (write_attn) k_passB<<<gB, T>>>(attn, E);
}

// round 5
// speedup vs baseline: 1.1600x; 1.1600x over previous
#include <cuda_runtime.h>

// GATv3Psi: per-edge logits -> (shift-free) segment softmax over dst -> aggregate.
// d_out layout: out[N], attn[E], pair_pred[E,2].

#define K2 16              // 2 * K_EIG
static const int NMAX = 100000;
static const int EMAX = 3200000;

__device__ int   g_is64;
__device__ int   g_dst32[EMAX];
__device__ float g_ex [EMAX];    // exp(score)
__device__ float g_den[NMAX];
__device__ float g_num[NMAX];
__device__ float g_invden[NMAX];

// Detect int64 vs int32 edge_index (JAX x64-disabled silently downcasts).
__global__ void k_detect(const void* ei, int N) {
    const long long* p = (const long long*)ei;
    int ok = 1;
    #pragma unroll
    for (int i = 0; i < 8; i++) {
        long long v = p[i];
        if (v < 0 || v >= (long long)N) { ok = 0; break; }
    }
    g_is64 = ok;
}

__global__ void k_init(int N) {
    int i = blockIdx.x * blockDim.x + threadIdx.x;
    if (i < N) { g_den[i] = 0.0f; g_num[i] = 0.0f; }
}

// Pass A: per-edge logits, pair_pred, ex = exp(l0-l1); atomically accumulate
// den[d] += ex and num[d] += ex * w0 * x[src] (separate arrays -> spread LTS
// contention). Emit int32 dst for pass B.
__global__ __launch_bounds__(256) void k_passA(
        const float* __restrict__ x,
        const void*  __restrict__ ei,
        const float* __restrict__ ea,
        const float* __restrict__ W,
        const float* __restrict__ Wn,
        const float* __restrict__ We,
        float* __restrict__ pair_pred,
        int E, int write_pp) {
    __shared__ float sWe[K2 * 2];
    __shared__ float sWn[4];
    __shared__ float sW0;
    if (threadIdx.x < K2 * 2) sWe[threadIdx.x] = We[threadIdx.x];
    if (threadIdx.x >= 32 && threadIdx.x < 36) sWn[threadIdx.x - 32] = Wn[threadIdx.x - 32];
    if (threadIdx.x == 36) sW0 = W[0];
    __syncthreads();

    int e = blockIdx.x * blockDim.x + threadIdx.x;
    if (e >= E) return;

    int s, d;
    if (g_is64) {
        const long long* p = (const long long*)ei;
        s = (int)p[e];
        d = (int)p[(long long)E + e];
    } else {
        const int* p = (const int*)ei;
        s = p[e];
        d = p[E + e];
    }
    g_dst32[e] = d;

    float xs = __ldg(&x[s]);
    float xd = __ldg(&x[d]);
    float l0 = xs * sWn[0] + xd * sWn[2];
    float l1 = xs * sWn[1] + xd * sWn[3];
    const float4* eap = (const float4*)(ea + (size_t)e * K2);
    #pragma unroll
    for (int i = 0; i < K2 / 4; i++) {
        float4 v = __ldg(&eap[i]);
        l0 = fmaf(v.x, sWe[(4*i+0)*2+0], l0);
        l1 = fmaf(v.x, sWe[(4*i+0)*2+1], l1);
        l0 = fmaf(v.y, sWe[(4*i+1)*2+0], l0);
        l1 = fmaf(v.y, sWe[(4*i+1)*2+1], l1);
        l0 = fmaf(v.z, sWe[(4*i+2)*2+0], l0);
        l1 = fmaf(v.z, sWe[(4*i+2)*2+1], l1);
        l0 = fmaf(v.w, sWe[(4*i+3)*2+0], l0);
        l1 = fmaf(v.w, sWe[(4*i+3)*2+1], l1);
    }
    l0 = fmaxf(l0, 0.2f * l0);   // leaky_relu(., 0.2)
    l1 = fmaxf(l1, 0.2f * l1);
    if (write_pp) ((float2*)pair_pred)[e] = make_float2(l0, l1);

    float ex = __expf(l0 - l1);  // shift-free: |l0-l1| small, no overflow risk
    g_ex[e] = ex;
    atomicAdd(&g_den[d], ex);
    atomicAdd(&g_num[d], ex * sW0 * xs);
}

// Node pass: out[i] = num * inv; stash inv for pass B.
__global__ void k_node(float* __restrict__ out, int N) {
    int i = blockIdx.x * blockDim.x + threadIdx.x;
    if (i < N) {
        float inv = 1.0f / (g_den[i] + 1e-16f);
        g_invden[i] = inv;
        out[i] = g_num[i] * inv;
    }
}

// Pass B: attn[e] = ex * inv_den[dst]. 4 edges/thread, vectorized, no divides.
__global__ __launch_bounds__(256) void k_passB(float* __restrict__ attn, int E) {
    int e = (blockIdx.x * blockDim.x + threadIdx.x) * 4;
    if (e + 3 < E) {
        float4 ex = *(const float4*)&g_ex[e];
        int4   d  = *(const int4*)&g_dst32[e];
        float4 a;
        a.x = ex.x * __ldg(&g_invden[d.x]);
        a.y = ex.y * __ldg(&g_invden[d.y]);
        a.z = ex.z * __ldg(&g_invden[d.z]);
        a.w = ex.w * __ldg(&g_invden[d.w]);
        *(float4*)&attn[e] = a;
    } else {
        for (; e < E; e++) attn[e] = g_ex[e] * __ldg(&g_invden[g_dst32[e]]);
    }
}

extern "C" void kernel_launch(void* const* d_in, const int* in_sizes, int n_in,
                              void* d_out, int out_size) {
    const float* x  = (const float*)d_in[0];
    const void*  ei = d_in[1];
    const float* ea = (const float*)d_in[2];
    const float* W  = (const float*)d_in[3];
    const float* Wn = (const float*)d_in[4];
    const float* We = (const float*)d_in[5];

    int N = in_sizes[0];          // x is [N, 1]
    int E = in_sizes[2] / K2;     // edge_attr is [E, 16]

    float* out  = (float*)d_out;
    float* attn = out + N;
    float* pp   = attn + E;
    int write_attn = (out_size >= N + E)     ? 1 : 0;
    int write_pp   = (out_size >= N + 3 * E) ? 1 : 0;

    const int T = 256;
    int gN = (N + T - 1) / T;
    int gE = (E + T - 1) / T;
    int gB = (E / 4 + T) / T;

    k_detect<<<1, 1>>>(ei, N);
    k_init  <<<gN, T>>>(N);
    k_passA <<<gE, T>>>(x, ei, ea, W, Wn, We, pp, E, write_pp);
    k_node  <<<gN, T>>>(out, N);
    if (write_attn) k_passB<<<gB, T>>>(attn, E);
}

// round 7
// speedup vs baseline: 1.2312x; 1.0613x over previous
#include <cuda_runtime.h>

// GATv3Psi: per-edge logits -> (shift-free) segment softmax over dst -> aggregate.
// d_out layout: out[N], attn[E], pair_pred[E,2].

#define K2 16              // 2 * K_EIG
static const int NMAX = 100000;
static const int EMAX = 3200000;

__device__ int   g_is64;
__device__ int   g_dst32[EMAX];
__device__ float g_ex [EMAX];    // only used when pair_pred is not emitted
__device__ float g_den[NMAX];
__device__ float g_num[NMAX];
__device__ float g_invden[NMAX];

// Init accumulators; thread 0 also detects int64 vs int32 edge_index
// (JAX x64-disabled silently downcasts int64 -> int32).
__global__ void k_init(const void* ei, int N) {
    int i = blockIdx.x * blockDim.x + threadIdx.x;
    if (i < N) { g_den[i] = 0.0f; g_num[i] = 0.0f; }
    if (blockIdx.x == 0 && threadIdx.x == 0) {
        const long long* p = (const long long*)ei;
        int ok = 1;
        #pragma unroll
        for (int j = 0; j < 8; j++) {
            long long v = p[j];
            if (v < 0 || v >= (long long)N) { ok = 0; break; }
        }
        g_is64 = ok;
    }
}

// Pass A: per-edge logits, pair_pred, ex = exp(l0-l1); atomic den/num accumulate
// (separate arrays -> spread LTS contention). Streaming hints keep L2 for x/atomics.
__global__ __launch_bounds__(256) void k_passA(
        const float* __restrict__ x,
        const void*  __restrict__ ei,
        const float* __restrict__ ea,
        const float* __restrict__ Wn,
        const float* __restrict__ We,
        float* __restrict__ pair_pred,
        int E, int write_pp) {
    __shared__ float sWe[K2 * 2];
    __shared__ float sWn[4];
    if (threadIdx.x < K2 * 2) sWe[threadIdx.x] = We[threadIdx.x];
    if (threadIdx.x >= 32 && threadIdx.x < 36) sWn[threadIdx.x - 32] = Wn[threadIdx.x - 32];
    __syncthreads();

    int e = blockIdx.x * blockDim.x + threadIdx.x;
    if (e >= E) return;

    int s, d;
    if (g_is64) {
        const long long* p = (const long long*)ei;
        s = (int)__ldcs(&p[e]);
        d = (int)__ldcs(&p[(long long)E + e]);
    } else {
        const int* p = (const int*)ei;
        s = __ldcs(&p[e]);
        d = __ldcs(&p[E + e]);
    }
    __stcs(&g_dst32[e], d);

    float xs = __ldg(&x[s]);
    float xd = __ldg(&x[d]);
    float l0 = xs * sWn[0] + xd * sWn[2];
    float l1 = xs * sWn[1] + xd * sWn[3];
    const float4* eap = (const float4*)(ea + (size_t)e * K2);
    #pragma unroll
    for (int i = 0; i < K2 / 4; i++) {
        float4 v = __ldcs(&eap[i]);
        l0 = fmaf(v.x, sWe[(4*i+0)*2+0], l0);
        l1 = fmaf(v.x, sWe[(4*i+0)*2+1], l1);
        l0 = fmaf(v.y, sWe[(4*i+1)*2+0], l0);
        l1 = fmaf(v.y, sWe[(4*i+1)*2+1], l1);
        l0 = fmaf(v.z, sWe[(4*i+2)*2+0], l0);
        l1 = fmaf(v.z, sWe[(4*i+2)*2+1], l1);
        l0 = fmaf(v.w, sWe[(4*i+3)*2+0], l0);
        l1 = fmaf(v.w, sWe[(4*i+3)*2+1], l1);
    }
    l0 = fmaxf(l0, 0.2f * l0);   // leaky_relu(., 0.2)
    l1 = fmaxf(l1, 0.2f * l1);

    float ex = __expf(l0 - l1);  // shift-free: |l0-l1| small, no overflow risk
    if (write_pp) {
        __stcs((float2*)pair_pred + e, make_float2(l0, l1));
    } else {
        __stcs(&g_ex[e], ex);
    }
    atomicAdd(&g_den[d], ex);
    atomicAdd(&g_num[d], ex * xs);       // w0 folded into k_node
}

// Node pass: out[i] = w0 * num * inv; stash inv for pass B.
__global__ void k_node(const float* __restrict__ W, float* __restrict__ out, int N) {
    int i = blockIdx.x * blockDim.x + threadIdx.x;
    if (i < N) {
        float inv = 1.0f / (g_den[i] + 1e-16f);
        g_invden[i] = inv;
        out[i] = __ldg(&W[0]) * g_num[i] * inv;
    }
}

// Pass B: attn[e] = exp(pp0-pp1) * inv_den[dst]. 4 edges/thread, no divides.
__global__ __launch_bounds__(256) void k_passB(const float* __restrict__ pp,
                                               float* __restrict__ attn,
                                               int E, int has_pp) {
    int e = (blockIdx.x * blockDim.x + threadIdx.x) * 4;
    if (e + 3 < E) {
        int4 d = *(const int4*)&g_dst32[e];
        float4 ex;
        if (has_pp) {
            float4 p01 = __ldcs((const float4*)(pp + (size_t)e * 2));
            float4 p23 = __ldcs((const float4*)(pp + (size_t)e * 2) + 1);
            ex.x = __expf(p01.x - p01.y);
            ex.y = __expf(p01.z - p01.w);
            ex.z = __expf(p23.x - p23.y);
            ex.w = __expf(p23.z - p23.w);
        } else {
            ex = *(const float4*)&g_ex[e];
        }
        float4 a;
        a.x = ex.x * __ldg(&g_invden[d.x]);
        a.y = ex.y * __ldg(&g_invden[d.y]);
        a.z = ex.z * __ldg(&g_invden[d.z]);
        a.w = ex.w * __ldg(&g_invden[d.w]);
        __stcs((float4*)&attn[e], a);
    } else {
        for (; e < E; e++) {
            float ex = has_pp ? __expf(pp[e*2] - pp[e*2+1]) : g_ex[e];
            attn[e] = ex * __ldg(&g_invden[g_dst32[e]]);
        }
    }
}

extern "C" void kernel_launch(void* const* d_in, const int* in_sizes, int n_in,
                              void* d_out, int out_size) {
    const float* x  = (const float*)d_in[0];
    const void*  ei = d_in[1];
    const float* ea = (const float*)d_in[2];
    const float* W  = (const float*)d_in[3];
    const float* Wn = (const float*)d_in[4];
    const float* We = (const float*)d_in[5];

    int N = in_sizes[0];          // x is [N, 1]
    int E = in_sizes[2] / K2;     // edge_attr is [E, 16]

    float* out  = (float*)d_out;
    float* attn = out + N;
    float* pp   = attn + E;
    int write_attn = (out_size >= N + E)     ? 1 : 0;
    int write_pp   = (out_size >= N + 3 * E) ? 1 : 0;

    const int T = 256;
    int gN = (N + T - 1) / T;
    int gE = (E + T - 1) / T;
    int gB = (E / 4 + T) / T;

    k_init  <<<gN, T>>>(ei, N);
    k_passA <<<gE, T>>>(x, ei, ea, Wn, We, pp, E, write_pp);
    k_node  <<<gN, T>>>(W, out, N);
    if (write_attn) k_passB<<<gB, T>>>(pp, attn, E, write_pp);
}

// round 10
// speedup vs baseline: 1.2612x; 1.0244x over previous
#include <cuda_runtime.h>

// GATv3Psi: per-edge logits -> (shift-free) segment softmax over dst -> aggregate.
// d_out layout: out[N], attn[E], pair_pred[E,2].

#define K2 16              // 2 * K_EIG
static const int NMAX = 100000;
static const int EMAX = 3200000;

__device__ int   g_is64;
__device__ int   g_dst32[EMAX];
__device__ float g_ex [EMAX];    // only used when pair_pred is not emitted
__device__ float g_den[NMAX];
__device__ float g_num[NMAX];

// Init accumulators; thread 0 also detects int64 vs int32 edge_index
// (JAX x64-disabled silently downcasts int64 -> int32).
__global__ void k_init(const void* ei, int N) {
    int i = blockIdx.x * blockDim.x + threadIdx.x;
    if (i < N) { g_den[i] = 0.0f; g_num[i] = 0.0f; }
    if (blockIdx.x == 0 && threadIdx.x == 0) {
        const long long* p = (const long long*)ei;
        int ok = 1;
        #pragma unroll
        for (int j = 0; j < 8; j++) {
            long long v = p[j];
            if (v < 0 || v >= (long long)N) { ok = 0; break; }
        }
        g_is64 = ok;
    }
}

// Pass A: per-edge logits, pair_pred, ex = exp(l0-l1); atomic den/num accumulate
// (separate arrays -> spread LTS contention). Streaming hints keep L2 for x/atomics.
__global__ __launch_bounds__(256) void k_passA(
        const float* __restrict__ x,
        const void*  __restrict__ ei,
        const float* __restrict__ ea,
        const float* __restrict__ Wn,
        const float* __restrict__ We,
        float* __restrict__ pair_pred,
        int E, int write_pp) {
    __shared__ float sWe[K2 * 2];
    __shared__ float sWn[4];
    if (threadIdx.x < K2 * 2) sWe[threadIdx.x] = We[threadIdx.x];
    if (threadIdx.x >= 32 && threadIdx.x < 36) sWn[threadIdx.x - 32] = Wn[threadIdx.x - 32];
    __syncthreads();

    int e = blockIdx.x * blockDim.x + threadIdx.x;
    if (e >= E) return;

    int s, d;
    if (g_is64) {
        const long long* p = (const long long*)ei;
        s = (int)__ldcs(&p[e]);
        d = (int)__ldcs(&p[(long long)E + e]);
    } else {
        const int* p = (const int*)ei;
        s = __ldcs(&p[e]);
        d = __ldcs(&p[E + e]);
    }
    __stcs(&g_dst32[e], d);

    float xs = __ldg(&x[s]);
    float xd = __ldg(&x[d]);
    float l0 = xs * sWn[0] + xd * sWn[2];
    float l1 = xs * sWn[1] + xd * sWn[3];
    const float4* eap = (const float4*)(ea + (size_t)e * K2);
    #pragma unroll
    for (int i = 0; i < K2 / 4; i++) {
        float4 v = __ldcs(&eap[i]);
        l0 = fmaf(v.x, sWe[(4*i+0)*2+0], l0);
        l1 = fmaf(v.x, sWe[(4*i+0)*2+1], l1);
        l0 = fmaf(v.y, sWe[(4*i+1)*2+0], l0);
        l1 = fmaf(v.y, sWe[(4*i+1)*2+1], l1);
        l0 = fmaf(v.z, sWe[(4*i+2)*2+0], l0);
        l1 = fmaf(v.z, sWe[(4*i+2)*2+1], l1);
        l0 = fmaf(v.w, sWe[(4*i+3)*2+0], l0);
        l1 = fmaf(v.w, sWe[(4*i+3)*2+1], l1);
    }
    l0 = fmaxf(l0, 0.2f * l0);   // leaky_relu(., 0.2)
    l1 = fmaxf(l1, 0.2f * l1);

    float ex = __expf(l0 - l1);  // shift-free: |l0-l1| small, no overflow risk
    if (write_pp) {
        __stcs((float2*)pair_pred + e, make_float2(l0, l1));
    } else {
        __stcs(&g_ex[e], ex);
    }
    atomicAdd(&g_den[d], ex);
    atomicAdd(&g_num[d], ex * xs);       // w0 folded into node path of k_finish
}

// Fused finish: one launch, depends only on passA.
//   blocks [0, gB):       attn[e] = ex * 1/(den[dst]+eps)  (4 edges/thread)
//   blocks [gB, gB+gN4):  out[i]  = w0 * num[i]/(den[i]+eps) (4 nodes/thread)
__global__ __launch_bounds__(256) void k_finish(
        const float* __restrict__ pp,
        const float* __restrict__ W,
        float* __restrict__ attn,
        float* __restrict__ out,
        int E, int N, int gB, int has_pp) {
    if ((int)blockIdx.x < gB) {
        int e = (blockIdx.x * blockDim.x + threadIdx.x) * 4;
        if (e + 3 < E) {
            int4 d = *(const int4*)&g_dst32[e];
            float4 ex;
            if (has_pp) {
                float4 p01 = __ldcs((const float4*)(pp + (size_t)e * 2));
                float4 p23 = __ldcs((const float4*)(pp + (size_t)e * 2) + 1);
                ex.x = __expf(p01.x - p01.y);
                ex.y = __expf(p01.z - p01.w);
                ex.z = __expf(p23.x - p23.y);
                ex.w = __expf(p23.z - p23.w);
            } else {
                ex = *(const float4*)&g_ex[e];
            }
            float4 a;
            a.x = __fdividef(ex.x, __ldg(&g_den[d.x]) + 1e-16f);
            a.y = __fdividef(ex.y, __ldg(&g_den[d.y]) + 1e-16f);
            a.z = __fdividef(ex.z, __ldg(&g_den[d.z]) + 1e-16f);
            a.w = __fdividef(ex.w, __ldg(&g_den[d.w]) + 1e-16f);
            __stcs((float4*)&attn[e], a);
        } else {
            for (; e < E; e++) {
                float ex = has_pp ? __expf(pp[e*2] - pp[e*2+1]) : g_ex[e];
                attn[e] = __fdividef(ex, __ldg(&g_den[g_dst32[e]]) + 1e-16f);
            }
        }
    } else {
        float w0 = __ldg(&W[0]);
        int i = ((blockIdx.x - gB) * blockDim.x + threadIdx.x) * 4;
        if (i + 3 < N) {
            float4 den = *(const float4*)&g_den[i];
            float4 num = *(const float4*)&g_num[i];
            float4 o;
            o.x = w0 * __fdividef(num.x, den.x + 1e-16f);
            o.y = w0 * __fdividef(num.y, den.y + 1e-16f);
            o.z = w0 * __fdividef(num.z, den.z + 1e-16f);
            o.w = w0 * __fdividef(num.w, den.w + 1e-16f);
            *(float4*)&out[i] = o;
        } else {
            for (; i < N; i++) out[i] = w0 * __fdividef(g_num[i], g_den[i] + 1e-16f);
        }
    }
}

extern "C" void kernel_launch(void* const* d_in, const int* in_sizes, int n_in,
                              void* d_out, int out_size) {
    const float* x  = (const float*)d_in[0];
    const void*  ei = d_in[1];
    const float* ea = (const float*)d_in[2];
    const float* W  = (const float*)d_in[3];
    const float* Wn = (const float*)d_in[4];
    const float* We = (const float*)d_in[5];

    int N = in_sizes[0];          // x is [N, 1]
    int E = in_sizes[2] / K2;     // edge_attr is [E, 16]

    float* out  = (float*)d_out;
    float* attn = out + N;
    float* pp   = attn + E;
    int write_attn = (out_size >= N + E)     ? 1 : 0;
    int write_pp   = (out_size >= N + 3 * E) ? 1 : 0;

    const int T = 256;
    int gN  = (N + T - 1) / T;
    int gE  = (E + T - 1) / T;
    int gB  = write_attn ? (E / 4 + T) / T : 0;   // edge blocks (4 edges/thread)
    int gN4 = (N + 4 * T - 1) / (4 * T);          // node blocks (4 nodes/thread)

    k_init  <<<gN, T>>>(ei, N);
    k_passA <<<gE, T>>>(x, ei, ea, Wn, We, pp, E, write_pp);
    k_finish<<<gB + gN4, T>>>(pp, W, attn, out, E, N, gB, write_pp);
}

// round 11
// speedup vs baseline: 1.3952x; 1.1063x over previous
#include <cuda_runtime.h>

// GATv3Psi: per-edge logits -> (shift-free) segment softmax over dst -> aggregate.
// d_out layout: out[N], attn[E], pair_pred[E,2].

#define K2 16              // 2 * K_EIG
static const int NMAX = 100000;
static const int EMAX = 3200000;

__device__ int    g_is64;
__device__ int    g_dst32[EMAX];
__device__ float  g_ex[EMAX];    // only used when pair_pred is not emitted
__device__ float2 g_dn[NMAX];    // .x = den, .y = num  (single red.v2 target)

__device__ __forceinline__ void red_add_v2(float2* addr, float a, float b) {
    asm volatile("red.global.add.v2.f32 [%0], {%1, %2};"
                 :: "l"(addr), "f"(a), "f"(b) : "memory");
}

// Vectorized init: 2 nodes/thread (one float4 across two float2 cells).
// Thread 0 also detects int64 vs int32 edge_index (JAX x64 downcast).
__global__ void k_init(const void* ei, int N) {
    int i = (blockIdx.x * blockDim.x + threadIdx.x) * 2;
    if (i + 1 < N) {
        *(float4*)&g_dn[i] = make_float4(0.f, 0.f, 0.f, 0.f);
    } else if (i < N) {
        g_dn[i] = make_float2(0.f, 0.f);
    }
    if (blockIdx.x == 0 && threadIdx.x == 0) {
        const long long* p = (const long long*)ei;
        int ok = 1;
        #pragma unroll
        for (int j = 0; j < 8; j++) {
            long long v = p[j];
            if (v < 0 || v >= (long long)N) { ok = 0; break; }
        }
        g_is64 = ok;
    }
}

// Pass A: per-edge logits, pair_pred, ex = exp(l0-l1);
// single red.v2 {ex, ex*xs} accumulate per edge. Streaming hints on edge streams.
__global__ __launch_bounds__(256) void k_passA(
        const float* __restrict__ x,
        const void*  __restrict__ ei,
        const float* __restrict__ ea,
        const float* __restrict__ Wn,
        const float* __restrict__ We,
        float* __restrict__ pair_pred,
        int E, int write_pp) {
    __shared__ float sWe[K2 * 2];
    __shared__ float sWn[4];
    if (threadIdx.x < K2 * 2) sWe[threadIdx.x] = We[threadIdx.x];
    if (threadIdx.x >= 32 && threadIdx.x < 36) sWn[threadIdx.x - 32] = Wn[threadIdx.x - 32];
    __syncthreads();

    int e = blockIdx.x * blockDim.x + threadIdx.x;
    if (e >= E) return;

    int s, d;
    if (g_is64) {
        const long long* p = (const long long*)ei;
        s = (int)__ldcs(&p[e]);
        d = (int)__ldcs(&p[(long long)E + e]);
    } else {
        const int* p = (const int*)ei;
        s = __ldcs(&p[e]);
        d = __ldcs(&p[E + e]);
    }
    __stcs(&g_dst32[e], d);

    float xs = __ldg(&x[s]);
    float xd = __ldg(&x[d]);
    float l0 = xs * sWn[0] + xd * sWn[2];
    float l1 = xs * sWn[1] + xd * sWn[3];
    const float4* eap = (const float4*)(ea + (size_t)e * K2);
    #pragma unroll
    for (int i = 0; i < K2 / 4; i++) {
        float4 v = __ldcs(&eap[i]);
        l0 = fmaf(v.x, sWe[(4*i+0)*2+0], l0);
        l1 = fmaf(v.x, sWe[(4*i+0)*2+1], l1);
        l0 = fmaf(v.y, sWe[(4*i+1)*2+0], l0);
        l1 = fmaf(v.y, sWe[(4*i+1)*2+1], l1);
        l0 = fmaf(v.z, sWe[(4*i+2)*2+0], l0);
        l1 = fmaf(v.z, sWe[(4*i+2)*2+1], l1);
        l0 = fmaf(v.w, sWe[(4*i+3)*2+0], l0);
        l1 = fmaf(v.w, sWe[(4*i+3)*2+1], l1);
    }
    l0 = fmaxf(l0, 0.2f * l0);   // leaky_relu(., 0.2)
    l1 = fmaxf(l1, 0.2f * l1);

    float ex = __expf(l0 - l1);  // shift-free: |l0-l1| small, no overflow risk
    if (write_pp) {
        __stcs((float2*)pair_pred + e, make_float2(l0, l1));
    } else {
        __stcs(&g_ex[e], ex);
    }
    red_add_v2(&g_dn[d], ex, ex * xs);   // w0 folded into node path of k_finish
}

// Fused finish: one launch, depends only on passA.
//   blocks [0, gB):       attn[e] = ex / (den[dst]+eps)   (4 edges/thread)
//   blocks [gB, gB+gN2):  out[i]  = w0 * num[i]/(den[i]+eps) (2 nodes/thread)
__global__ __launch_bounds__(256) void k_finish(
        const float* __restrict__ pp,
        const float* __restrict__ W,
        float* __restrict__ attn,
        float* __restrict__ out,
        int E, int N, int gB, int has_pp) {
    if ((int)blockIdx.x < gB) {
        int e = (blockIdx.x * blockDim.x + threadIdx.x) * 4;
        if (e + 3 < E) {
            int4 d = *(const int4*)&g_dst32[e];
            float4 ex;
            if (has_pp) {
                float4 p01 = __ldcs((const float4*)(pp + (size_t)e * 2));
                float4 p23 = __ldcs((const float4*)(pp + (size_t)e * 2) + 1);
                ex.x = __expf(p01.x - p01.y);
                ex.y = __expf(p01.z - p01.w);
                ex.z = __expf(p23.x - p23.y);
                ex.w = __expf(p23.z - p23.w);
            } else {
                ex = *(const float4*)&g_ex[e];
            }
            float4 a;
            a.x = __fdividef(ex.x, __ldg(&g_dn[d.x].x) + 1e-16f);
            a.y = __fdividef(ex.y, __ldg(&g_dn[d.y].x) + 1e-16f);
            a.z = __fdividef(ex.z, __ldg(&g_dn[d.z].x) + 1e-16f);
            a.w = __fdividef(ex.w, __ldg(&g_dn[d.w].x) + 1e-16f);
            __stcs((float4*)&attn[e], a);
        } else {
            for (; e < E; e++) {
                float ex = has_pp ? __expf(pp[e*2] - pp[e*2+1]) : g_ex[e];
                attn[e] = __fdividef(ex, __ldg(&g_dn[g_dst32[e]].x) + 1e-16f);
            }
        }
    } else {
        float w0 = __ldg(&W[0]);
        int i = ((blockIdx.x - gB) * blockDim.x + threadIdx.x) * 2;
        if (i + 1 < N) {
            float4 v = *(const float4*)&g_dn[i];   // {den0,num0,den1,num1}
            float2 o;
            o.x = w0 * __fdividef(v.y, v.x + 1e-16f);
            o.y = w0 * __fdividef(v.w, v.z + 1e-16f);
            *(float2*)&out[i] = o;
        } else if (i < N) {
            float2 v = g_dn[i];
            out[i] = w0 * __fdividef(v.y, v.x + 1e-16f);
        }
    }
}

extern "C" void kernel_launch(void* const* d_in, const int* in_sizes, int n_in,
                              void* d_out, int out_size) {
    const float* x  = (const float*)d_in[0];
    const void*  ei = d_in[1];
    const float* ea = (const float*)d_in[2];
    const float* W  = (const float*)d_in[3];
    const float* Wn = (const float*)d_in[4];
    const float* We = (const float*)d_in[5];

    int N = in_sizes[0];          // x is [N, 1]
    int E = in_sizes[2] / K2;     // edge_attr is [E, 16]

    float* out  = (float*)d_out;
    float* attn = out + N;
    float* pp   = attn + E;
    int write_attn = (out_size >= N + E)     ? 1 : 0;
    int write_pp   = (out_size >= N + 3 * E) ? 1 : 0;

    const int T = 256;
    int gI  = (N / 2 + T) / T;                    // init: 2 nodes/thread
    int gE  = (E + T - 1) / T;
    int gB  = write_attn ? (E / 4 + T) / T : 0;   // edge blocks (4 edges/thread)
    int gN2 = (N + 2 * T - 1) / (2 * T);          // node blocks (2 nodes/thread)

    k_init  <<<gI, T>>>(ei, N);
    k_passA <<<gE, T>>>(x, ei, ea, Wn, We, pp, E, write_pp);
    k_finish<<<gB + gN2, T>>>(pp, W, attn, out, E, N, gB, write_pp);
}

// round 12
// speedup vs baseline: 1.4026x; 1.0053x over previous
#include <cuda_runtime.h>

// GATv3Psi: per-edge logits -> (shift-free) segment softmax over dst -> aggregate.
// d_out layout: out[N], attn[E], pair_pred[E,2].
// PDL: k_init (zeroing) hidden under k_passA's prefix; sync only before atomics.

#define K2 16              // 2 * K_EIG
static const int NMAX = 100000;
static const int EMAX = 3200000;

__device__ int    g_dst32[EMAX];
__device__ float  g_ex[EMAX];    // only used when pair_pred is not emitted
__device__ float2 g_dn[NMAX];    // .x = den, .y = num  (single red.v2 target)

__device__ __forceinline__ void red_add_v2(float2* addr, float a, float b) {
    asm volatile("red.global.add.v2.f32 [%0], {%1, %2};"
                 :: "l"(addr), "f"(a), "f"(b) : "memory");
}

// Pure memset of accumulators; releases dependent launch immediately.
__global__ void k_init(int N) {
    cudaTriggerProgrammaticLaunchCompletion();
    int i = (blockIdx.x * blockDim.x + threadIdx.x) * 2;
    if (i + 1 < N) {
        *(float4*)&g_dn[i] = make_float4(0.f, 0.f, 0.f, 0.f);
    } else if (i < N) {
        g_dn[i] = make_float2(0.f, 0.f);
    }
}

// Pass A: per-edge logits, pair_pred, ex = exp(l0-l1);
// single red.v2 {ex, ex*xs} accumulate per edge. Grid-sync on k_init only
// right before the atomic so the whole prefix overlaps the memset.
__global__ __launch_bounds__(256) void k_passA(
        const float* __restrict__ x,
        const void*  __restrict__ ei,
        const float* __restrict__ ea,
        const float* __restrict__ Wn,
        const float* __restrict__ We,
        float* __restrict__ pair_pred,
        int E, int N, int write_pp) {
    __shared__ float sWe[K2 * 2];
    __shared__ float sWn[4];
    __shared__ int   sIs64;
    if (threadIdx.x < K2 * 2) sWe[threadIdx.x] = We[threadIdx.x];
    if (threadIdx.x >= 32 && threadIdx.x < 36) sWn[threadIdx.x - 32] = Wn[threadIdx.x - 32];
    if (threadIdx.x == 64) {
        // Detect int64 vs int32 edge_index (JAX x64-disabled silently downcasts):
        // int32 data read as int64 yields values outside [0, N) with high prob.
        const long long* p = (const long long*)ei;
        int ok = 1;
        #pragma unroll
        for (int j = 0; j < 8; j++) {
            long long v = p[j];
            if (v < 0 || v >= (long long)N) { ok = 0; break; }
        }
        sIs64 = ok;
    }
    __syncthreads();

    int e = blockIdx.x * blockDim.x + threadIdx.x;
    if (e >= E) return;

    int s, d;
    if (sIs64) {
        const long long* p = (const long long*)ei;
        s = (int)__ldcs(&p[e]);
        d = (int)__ldcs(&p[(long long)E + e]);
    } else {
        const int* p = (const int*)ei;
        s = __ldcs(&p[e]);
        d = __ldcs(&p[E + e]);
    }
    __stcs(&g_dst32[e], d);

    float xs = __ldg(&x[s]);
    float xd = __ldg(&x[d]);
    float l0 = xs * sWn[0] + xd * sWn[2];
    float l1 = xs * sWn[1] + xd * sWn[3];
    const float4* eap = (const float4*)(ea + (size_t)e * K2);
    #pragma unroll
    for (int i = 0; i < K2 / 4; i++) {
        float4 v = __ldcs(&eap[i]);
        l0 = fmaf(v.x, sWe[(4*i+0)*2+0], l0);
        l1 = fmaf(v.x, sWe[(4*i+0)*2+1], l1);
        l0 = fmaf(v.y, sWe[(4*i+1)*2+0], l0);
        l1 = fmaf(v.y, sWe[(4*i+1)*2+1], l1);
        l0 = fmaf(v.z, sWe[(4*i+2)*2+0], l0);
        l1 = fmaf(v.z, sWe[(4*i+2)*2+1], l1);
        l0 = fmaf(v.w, sWe[(4*i+3)*2+0], l0);
        l1 = fmaf(v.w, sWe[(4*i+3)*2+1], l1);
    }
    l0 = fmaxf(l0, 0.2f * l0);   // leaky_relu(., 0.2)
    l1 = fmaxf(l1, 0.2f * l1);

    float ex = __expf(l0 - l1);  // shift-free: |l0-l1| small, no overflow risk
    if (write_pp) {
        __stcs((float2*)pair_pred + e, make_float2(l0, l1));
    } else {
        __stcs(&g_ex[e], ex);
    }
    cudaGridDependencySynchronize();     // g_dn zeroing complete from here on
    red_add_v2(&g_dn[d], ex, ex * xs);   // w0 folded into node path of k_finish
}

// Fused finish: one launch, depends on all of passA (sync at top).
//   blocks [0, gB):       attn[e] = ex / (den[dst]+eps)   (4 edges/thread)
//   blocks [gB, gB+gN2):  out[i]  = w0 * num[i]/(den[i]+eps) (2 nodes/thread)
__global__ __launch_bounds__(256) void k_finish(
        const float* __restrict__ pp,
        const float* __restrict__ W,
        float* __restrict__ attn,
        float* __restrict__ out,
        int E, int N, int gB, int has_pp) {
    cudaGridDependencySynchronize();
    if ((int)blockIdx.x < gB) {
        int e = (blockIdx.x * blockDim.x + threadIdx.x) * 4;
        if (e + 3 < E) {
            int4 d = *(const int4*)&g_dst32[e];
            float4 ex;
            if (has_pp) {
                float4 p01 = __ldcs((const float4*)(pp + (size_t)e * 2));
                float4 p23 = __ldcs((const float4*)(pp + (size_t)e * 2) + 1);
                ex.x = __expf(p01.x - p01.y);
                ex.y = __expf(p01.z - p01.w);
                ex.z = __expf(p23.x - p23.y);
                ex.w = __expf(p23.z - p23.w);
            } else {
                ex = *(const float4*)&g_ex[e];
            }
            float4 a;
            a.x = __fdividef(ex.x, __ldg(&g_dn[d.x].x) + 1e-16f);
            a.y = __fdividef(ex.y, __ldg(&g_dn[d.y].x) + 1e-16f);
            a.z = __fdividef(ex.z, __ldg(&g_dn[d.z].x) + 1e-16f);
            a.w = __fdividef(ex.w, __ldg(&g_dn[d.w].x) + 1e-16f);
            __stcs((float4*)&attn[e], a);
        } else {
            for (; e < E; e++) {
                float ex = has_pp ? __expf(pp[e*2] - pp[e*2+1]) : g_ex[e];
                attn[e] = __fdividef(ex, __ldg(&g_dn[g_dst32[e]].x) + 1e-16f);
            }
        }
    } else {
        float w0 = __ldg(&W[0]);
        int i = ((blockIdx.x - gB) * blockDim.x + threadIdx.x) * 2;
        if (i + 1 < N) {
            float4 v = *(const float4*)&g_dn[i];   // {den0,num0,den1,num1}
            float2 o;
            o.x = w0 * __fdividef(v.y, v.x + 1e-16f);
            o.y = w0 * __fdividef(v.w, v.z + 1e-16f);
            *(float2*)&out[i] = o;
        } else if (i < N) {
            float2 v = g_dn[i];
            out[i] = w0 * __fdividef(v.y, v.x + 1e-16f);
        }
    }
}

extern "C" void kernel_launch(void* const* d_in, const int* in_sizes, int n_in,
                              void* d_out, int out_size) {
    const float* x  = (const float*)d_in[0];
    const void*  ei = d_in[1];
    const float* ea = (const float*)d_in[2];
    const float* W  = (const float*)d_in[3];
    const float* Wn = (const float*)d_in[4];
    const float* We = (const float*)d_in[5];

    int N = in_sizes[0];          // x is [N, 1]
    int E = in_sizes[2] / K2;     // edge_attr is [E, 16]

    float* out  = (float*)d_out;
    float* attn = out + N;
    float* pp   = attn + E;
    int write_attn = (out_size >= N + E)     ? 1 : 0;
    int write_pp   = (out_size >= N + 3 * E) ? 1 : 0;

    const unsigned T = 256;
    unsigned gI  = (N / 2 + T) / T;                    // init: 2 nodes/thread
    unsigned gE  = (E + T - 1) / T;
    int      gB  = write_attn ? (E / 4 + (int)T) / (int)T : 0;
    unsigned gN2 = (N + 2 * T - 1) / (2 * T);

    k_init<<<gI, T>>>(N);

    cudaLaunchAttribute attrs[1];
    attrs[0].id = cudaLaunchAttributeProgrammaticStreamSerialization;
    attrs[0].val.programmaticStreamSerializationAllowed = 1;

    cudaLaunchConfig_t cfgA = {};
    cfgA.gridDim  = {gE, 1, 1};
    cfgA.blockDim = {T, 1, 1};
    cfgA.attrs = attrs;
    cfgA.numAttrs = 1;
    cudaLaunchKernelEx(&cfgA, k_passA, x, (const void*)ei, ea, Wn, We, pp, E, N, write_pp);

    cudaLaunchConfig_t cfgF = {};
    cfgF.gridDim  = {(unsigned)gB + gN2, 1, 1};
    cfgF.blockDim = {T, 1, 1};
    cfgF.attrs = attrs;
    cfgF.numAttrs = 1;
    cudaLaunchKernelEx(&cfgF, k_finish, (const float*)pp, W, attn, out, E, N, gB, write_pp);
}